// round 16
// baseline (speedup 1.0000x reference)
#include <cuda_runtime.h>
#include <cuda_bf16.h>
#include <cstdint>
#include <math.h>

// ---------------- problem constants ----------------
#define NB    8
#define DD    256
#define HEADS 8
#define PN    3136
#define CH    56
#define WS    7
#define P     49
#define WIN   64
#define HD    2048
#define PIX   224
#define NPAD  3200
#define PNQ   3328                    // 64 windows * 52 (aligned window stride)

#define BATCH_X   ((long)DD*PN)

// ---------------- static scratch -------------------
// K,Q in window-transposed bf16 hi/lo: [nb][s=K/Q][h][win][p(52)][d(256)]
__device__ __align__(16) __nv_bfloat16 g_kqt_hi[(long)NB * 2 * HEADS * WIN * 52 * 256];
__device__ __align__(16) __nv_bfloat16 g_kqt_lo[(long)NB * 2 * HEADS * WIN * 52 * 256];
// V in [nb][h*256+d][pnq] bf16 hi/lo
__device__ __align__(16) __nv_bfloat16 g_v_hi[(long)NB * HD * PNQ];
__device__ __align__(16) __nv_bfloat16 g_v_lo[(long)NB * HD * PNQ];
__device__ __align__(16) __nv_bfloat16 g_Wc_hi[6144 * 256];
__device__ __align__(16) __nv_bfloat16 g_Wc_lo[6144 * 256];
__device__ __align__(16) __nv_bfloat16 g_Wo_hi[256 * 2048];
__device__ __align__(16) __nv_bfloat16 g_Wo_lo[256 * 2048];
__device__ float g_bias_c[6144];
__device__ __align__(16) __nv_bfloat16 g_xt_hi[(long)NB * NPAD * DD];
__device__ __align__(16) __nv_bfloat16 g_xt_lo[(long)NB * NPAD * DD];
__device__ __align__(16) __nv_bfloat16 g_at_hi[(long)NB * NPAD * HD];
__device__ __align__(16) __nv_bfloat16 g_at_lo[(long)NB * NPAD * HD];

// ---------------- PTX helpers ----------------------
__device__ __forceinline__ uint32_t smem_u32(const void* p) {
    uint32_t a;
    asm("{ .reg .u64 t; cvta.to.shared.u64 t, %1; cvt.u32.u64 %0, t; }"
        : "=r"(a) : "l"(p));
    return a;
}

#define CP16(dst, src) \
    asm volatile("cp.async.cg.shared.global [%0], [%1], 16;" :: "r"(dst), "l"(src))
#define CP8(dst, src) \
    asm volatile("cp.async.ca.shared.global [%0], [%1], 8;" :: "r"(dst), "l"(src))
#define CP_COMMIT() asm volatile("cp.async.commit_group;" ::: "memory")
#define CP_WAIT(n)  asm volatile("cp.async.wait_group %0;" :: "n"(n) : "memory")

#define LDSM4(r, addr) \
    asm volatile("ldmatrix.sync.aligned.m8n8.x4.shared.b16 {%0,%1,%2,%3}, [%4];" \
        : "=r"((r)[0]), "=r"((r)[1]), "=r"((r)[2]), "=r"((r)[3]) : "r"(addr))

#define MMA_BF16(c, a, b0, b1) \
    asm volatile("mma.sync.aligned.m16n8k16.row.col.f32.bf16.bf16.f32 " \
        "{%0,%1,%2,%3}, {%4,%5,%6,%7}, {%8,%9}, {%0,%1,%2,%3};" \
        : "+f"((c)[0]), "+f"((c)[1]), "+f"((c)[2]), "+f"((c)[3]) \
        : "r"((a)[0]), "r"((a)[1]), "r"((a)[2]), "r"((a)[3]), "r"(b0), "r"(b1))

__device__ __forceinline__ void split_store(float x, __nv_bfloat16* hi,
                                            __nv_bfloat16* lo, long idx) {
    __nv_bfloat16 h = __float2bfloat16(x);
    hi[idx] = h;
    lo[idx] = __float2bfloat16(x - __bfloat162float(h));
}

// window-ordered column -> spatial patch index
__device__ __forceinline__ int spatial_col(int c) {
    int win = c / 49, pos = c - win * 49;
    int wy = win >> 3, wx = win & 7;
    int py = pos / 7,  px = pos - py * 7;
    return (wy * 7 + py) * CH + (wx * 7 + px);
}

// ------- fused shift + transpose + hi/lo convert -------
__global__ void shift_conv_kernel(const float* __restrict__ in,
                                  __nv_bfloat16* __restrict__ hi,
                                  __nv_bfloat16* __restrict__ lo) {
    long idx = (long)blockIdx.x * blockDim.x + threadIdx.x;
    if (idx >= (long)NB * PN * DD) return;
    int d  = (int)(idx % DD);
    int c  = (int)((idx / DD) % PN);
    int nb = (int)(idx / ((long)DD * PN));
    int win = c / 49, pos = c - win * 49;
    int wy = win >> 3, wx = win & 7;
    int py = pos / 7,  px = pos - py * 7;
    int i = wy * 7 + py, j = wx * 7 + px;
    int ch = d >> 4;
    int r = i * 4 + ((d >> 2) & 3), s = j * 4 + (d & 3);
    int rs = (r + PIX - 3) % PIX;
    int ss = (s + PIX - 3) % PIX;
    int dp = (ch << 4) + ((rs & 3) << 2) + (ss & 3);
    int pp = (rs >> 2) * CH + (ss >> 2);
    float x = in[((long)nb * DD + dp) * PN + pp];
    __nv_bfloat16 h = __float2bfloat16(x);
    long o = ((long)nb * NPAD + c) * DD + d;
    hi[o] = h;
    lo[o] = __float2bfloat16(x - __bfloat162float(h));
}

// ------------- weight conversion -------------------
__global__ void convert_weights(const float* __restrict__ Wk, const float* __restrict__ Wq,
                                const float* __restrict__ Wv, const float* __restrict__ bk,
                                const float* __restrict__ bq, const float* __restrict__ bv,
                                const float* __restrict__ Wo) {
    const long NW = 6144L * 256, NO = 256L * 2048;
    long i = (long)blockIdx.x * blockDim.x + threadIdx.x;
    if (i < NW) {
        int row = (int)(i >> 8), col = (int)(i & 255);
        const float* src = (row < 2048) ? Wk : ((row < 4096) ? Wq : Wv);
        float x = src[(long)(row & 2047) * 256 + col];
        __nv_bfloat16 h = __float2bfloat16(x);
        g_Wc_hi[i] = h;
        g_Wc_lo[i] = __float2bfloat16(x - __bfloat162float(h));
    } else if (i < NW + NO) {
        long j = i - NW;
        float x = Wo[j];
        __nv_bfloat16 h = __float2bfloat16(x);
        g_Wo_hi[j] = h;
        g_Wo_lo[j] = __float2bfloat16(x - __bfloat162float(h));
    } else if (i < NW + NO + 6144) {
        int r = (int)(i - NW - NO);
        const float* sb = (r < 2048) ? bk : ((r < 4096) ? bq : bv);
        g_bias_c[r] = sb[r & 2047];
    }
}

// ------------- HMMA bf16x3 GEMM --------------------
// 2-stage cp.async pipeline, 2 CTAs/SM.  Template BN: 128 (proj, proven) or
// 64 (outproj — better wave balance: 800 blocks instead of 400).
// mode 0: proj -> writes K/Q transposed bf16 hi/lo + V bf16 hi/lo
// mode 1: outproj -> fp32 out with spatial permutation
#define TSTRIDE 40
#define ATILE_HALVES (128 * TSTRIDE)

template<int BN>
__global__ __launch_bounds__(256, 2) void gemm_kernel(
    const __nv_bfloat16* __restrict__ Ahi, const __nv_bfloat16* __restrict__ Alo,
    const __nv_bfloat16* __restrict__ Bhi, const __nv_bfloat16* __restrict__ Blo,
    const float* __restrict__ bias, float* __restrict__ Cbase,
    int K, long bStride, int mode)
{
    constexpr int BTILE_HALVES = BN * TSTRIDE;
    constexpr int STG = 2 * ATILE_HALVES + 2 * BTILE_HALVES;  // stage halves
    constexpr int MT = (BN == 128) ? 2 : 1;    // m-subtiles (16 rows) per warp
    constexpr int WROWS = MT * 16;

    extern __shared__ __nv_bfloat16 sh[];
    const int tid = threadIdx.x;
    const int lane = tid & 31;
    const int wid = tid >> 5;
    const int wm = (BN == 128) ? (wid & 3) : wid;
    const int wn = (BN == 128) ? (wid >> 2) : 0;
    const int z  = blockIdx.z;
    const int m0g = blockIdx.y * 128;
    const int n0g = blockIdx.x * BN;
    const int T = K >> 5;

    const __nv_bfloat16* srcs[4];
    srcs[0] = Ahi + (long)m0g * K;
    srcs[1] = Alo + (long)m0g * K;
    srcs[2] = Bhi + (long)z * bStride + (long)n0g * K;
    srcs[3] = Blo + (long)z * bStride + (long)n0g * K;

    const uint32_t smu = smem_u32(sh);
    const int ldr0 = tid >> 2;
    const int ldc0 = (tid & 3) << 3;

    float acc[MT][8][4];
#pragma unroll
    for (int a = 0; a < MT; a++)
#pragma unroll
        for (int b = 0; b < 8; b++)
#pragma unroll
            for (int cc = 0; cc < 4; cc++) acc[a][b][cc] = 0.f;

    const int a_r = wm * WROWS + ((lane >> 3) & 1) * 8 + (lane & 7);
    const int a_c = (lane >> 4) * 8;
    const int b_r = wn * 64 + (lane >> 4) * 8 + (lane & 7);
    const int b_c = ((lane >> 3) & 1) * 8;

    // ---- preload stage 0 ----
#pragma unroll
    for (int arr = 0; arr < 2; arr++) {       // A hi/lo: 128 rows
#pragma unroll
        for (int j = 0; j < 2; j++) {
            int r = ldr0 + j * 64;
            uint32_t dst = smu + (arr * ATILE_HALVES + r * TSTRIDE + ldc0) * 2;
            CP16(dst, srcs[arr] + (long)r * K + ldc0);
        }
    }
#pragma unroll
    for (int arr = 0; arr < 2; arr++) {       // B hi/lo: BN rows
#pragma unroll
        for (int j = 0; j < BN / 64; j++) {
            int r = ldr0 + j * 64;
            uint32_t dst = smu + (2 * ATILE_HALVES + arr * BTILE_HALVES
                                  + r * TSTRIDE + ldc0) * 2;
            CP16(dst, srcs[2 + arr] + (long)r * K + ldc0);
        }
    }
    CP_COMMIT();

    for (int t = 0; t < T; t++) {
        CP_WAIT(0);
        __syncthreads();
        if (t + 1 < T) {
            const int s2 = (t + 1) & 1;
#pragma unroll
            for (int arr = 0; arr < 2; arr++) {
#pragma unroll
                for (int j = 0; j < 2; j++) {
                    int r = ldr0 + j * 64;
                    uint32_t dst = smu + (s2 * STG + arr * ATILE_HALVES
                                          + r * TSTRIDE + ldc0) * 2;
                    CP16(dst, srcs[arr] + (long)r * K + (t + 1) * 32 + ldc0);
                }
            }
#pragma unroll
            for (int arr = 0; arr < 2; arr++) {
#pragma unroll
                for (int j = 0; j < BN / 64; j++) {
                    int r = ldr0 + j * 64;
                    uint32_t dst = smu + (s2 * STG + 2 * ATILE_HALVES
                                          + arr * BTILE_HALVES + r * TSTRIDE + ldc0) * 2;
                    CP16(dst, srcs[2 + arr] + (long)r * K + (t + 1) * 32 + ldc0);
                }
            }
            CP_COMMIT();
        }

        const uint32_t sb = smu + ((t & 1) * STG) * 2;
        const uint32_t sAh = sb;
        const uint32_t sAl = sb + ATILE_HALVES * 2;
        const uint32_t sBh = sb + 2 * ATILE_HALVES * 2;
        const uint32_t sBl = sb + (2 * ATILE_HALVES + BTILE_HALVES) * 2;

#pragma unroll
        for (int k16 = 0; k16 < 2; k16++) {
            uint32_t ah[MT][4], al[MT][4];
#pragma unroll
            for (int mt = 0; mt < MT; mt++) {
                uint32_t off = ((a_r + mt * 16) * TSTRIDE + a_c + k16 * 16) * 2;
                LDSM4(ah[mt], sAh + off);
                LDSM4(al[mt], sAl + off);
            }
#pragma unroll
            for (int nt2 = 0; nt2 < 4; nt2++) {
                uint32_t bh[4], bl[4];
                uint32_t off = ((b_r + nt2 * 16) * TSTRIDE + b_c + k16 * 16) * 2;
                LDSM4(bh, sBh + off);
                LDSM4(bl, sBl + off);
#pragma unroll
                for (int mt = 0; mt < MT; mt++) {
#pragma unroll
                    for (int sn = 0; sn < 2; sn++) {
                        float* cc = acc[mt][nt2 * 2 + sn];
                        MMA_BF16(cc, ah[mt], bh[sn * 2], bh[sn * 2 + 1]);
                        MMA_BF16(cc, ah[mt], bl[sn * 2], bl[sn * 2 + 1]);
                        MMA_BF16(cc, al[mt], bh[sn * 2], bh[sn * 2 + 1]);
                    }
                }
            }
        }
        __syncthreads();
    }

    // ---- epilogue ----
#pragma unroll
    for (int mt = 0; mt < MT; mt++) {
#pragma unroll
        for (int half = 0; half < 2; half++) {
            int m = m0g + wm * WROWS + mt * 16 + (lane >> 2) + half * 8;
            float bb = bias[m];
            if (mode == 0) {
                int s = m >> 11;            // 0=K 1=Q 2=V
                int hrow = m & 2047;        // h*256+d
                int d = hrow & 255;
                long kqbase = 0, vrow = 0;
                if (s < 2) kqbase = (((long)z * 2 + s) * 8 + (hrow >> 8)) * 64;
                else       vrow = ((long)z * HD + hrow) * PNQ;
#pragma unroll
                for (int nt = 0; nt < 8; nt++) {
                    int n = n0g + wn * 64 + nt * 8 + ((lane & 3) << 1);
                    if (n >= PN) continue;   // n even; n+1 < PN guaranteed
                    float v0 = acc[mt][nt][half * 2 + 0] + bb;
                    float v1 = acc[mt][nt][half * 2 + 1] + bb;
                    int w0 = n / 49, p0 = n - w0 * 49;
                    int n1 = n + 1;
                    int w1 = n1 / 49, p1 = n1 - w1 * 49;
                    if (s < 2) {
                        long i0 = ((kqbase + w0) * 52 + p0) * 256 + d;
                        long i1 = ((kqbase + w1) * 52 + p1) * 256 + d;
                        split_store(v0, g_kqt_hi, g_kqt_lo, i0);
                        split_store(v1, g_kqt_hi, g_kqt_lo, i1);
                    } else {
                        split_store(v0, g_v_hi, g_v_lo, vrow + w0 * 52 + p0);
                        split_store(v1, g_v_hi, g_v_lo, vrow + w1 * 52 + p1);
                    }
                }
            } else {
                float* C = Cbase + (long)z * BATCH_X;
                long rowoff = (long)m * PN;
#pragma unroll
                for (int nt = 0; nt < 8; nt++) {
                    int n = n0g + wn * 64 + nt * 8 + ((lane & 3) << 1);
                    if (n >= PN) continue;
                    float v0 = acc[mt][nt][half * 2 + 0] + bb;
                    float v1 = acc[mt][nt][half * 2 + 1] + bb;
                    C[rowoff + spatial_col(n)] = v0;
                    C[rowoff + spatial_col(n + 1)] = v1;
                }
            }
        }
    }
}

#define GEMM_SMEM_128 (2 * (2 * ATILE_HALVES + 2 * 128 * TSTRIDE) * 2)
#define GEMM_SMEM_64  (2 * (2 * ATILE_HALVES + 2 * 64 * TSTRIDE) * 2)

// ---------------- HMMA attention kernel ------------------
// Exact round-12 structure (measured 290.9us).
#define KST 136         // halves stride, Kt/Qt rows [p][d-chunk]; 272 B (16B mult)
#define AST 72          // halves stride, V rows [d][p]
#define SST 53          // floats stride for S matrix
#define WST 72          // halves stride, Wt rows ([q][p])
#define OST 260         // floats stride for output staging
#define ATTN_A_BYTES   73728
#define ATTN_S_BYTES   13568
#define ATTN_W_BYTES   9216
#define ATTN_SMEM_BYTES (ATTN_A_BYTES + ATTN_S_BYTES + 2 * ATTN_W_BYTES)

__global__ __launch_bounds__(256, 2) void attn_kernel(
    const float* __restrict__ rel_code,
    __nv_bfloat16* __restrict__ at_hi, __nv_bfloat16* __restrict__ at_lo)
{
    extern __shared__ char dyn[];
    __nv_bfloat16* A0  = (__nv_bfloat16*)dyn;
    float* Ssm  = (float*)(dyn + ATTN_A_BYTES);
    __nv_bfloat16* WHI = (__nv_bfloat16*)(dyn + ATTN_A_BYTES + ATTN_S_BYTES);
    __nv_bfloat16* WLO = WHI + 64 * WST;
    __shared__ float rel_s[169];
    __shared__ int   fm_s[49];

    const int g  = blockIdx.x;
    const int h  = blockIdx.y;
    const int nb = blockIdx.z;
    const int tid = threadIdx.x;
    const int lane = tid & 31;
    const int wid = tid >> 5;

    const long kbase = ((((long)nb * 2 + 0) * HEADS + h) * WIN + g) * 52 * 256;
    const long qbase = ((((long)nb * 2 + 1) * HEADS + h) * WIN + g) * 52 * 256;
    const long vbase = ((long)nb * HD + h * DD) * PNQ + g * 52;

    if (tid < 169) rel_s[tid] = rel_code[tid * HEADS + h];
    if (tid < P) {
        int gy = g >> 3, gx = g & 7;
        int ty = (tid * 37) >> 8, tx = tid - ty * 7;
        int rr = gy * 7 + ty, cc = gx * 7 + tx;
        int ry = (rr < 49) ? 0 : ((rr < 53) ? 1 : 2);
        int rx = (cc < 49) ? 0 : ((cc < 53) ? 1 : 2);
        fm_s[tid] = ry * 3 + rx;
    }

    const uint32_t sA = smem_u32(A0);
    const __nv_bfloat16* gsrc[4] = {
        g_kqt_hi + kbase, g_kqt_lo + kbase, g_kqt_hi + qbase, g_kqt_lo + qbase };

    const int wm = wid & 3;         // S: 4 p-warps (m-tiles of 16)
    const int wn = wid >> 2;        // S: 2 q-warps (n-tiles of 32)
    const int j8 = lane & 7;
    const int off1 = ((lane >> 3) & 1) << 3;
    const int off2 = ((lane >> 4) & 1) << 3;

    float sacc[4][4];
#pragma unroll
    for (int i = 0; i < 4; i++)
#pragma unroll
        for (int k = 0; k < 4; k++) sacc[i][k] = 0.f;

    // ---- phase 1: S = K^T Q, two d-chunks of 128 ----
    for (int c = 0; c < 2; c++) {
        __syncthreads();
        for (int i = tid; i < 4096; i += 256) {
            int arr = i >> 10, idx = i & 1023, row = idx >> 4, ch = idx & 15;
            if (row < 52) {
                uint32_t dst = sA + (arr * 64 * KST + row * KST) * 2 + ch * 16;
                const __nv_bfloat16* src = gsrc[arr] + row * 256 + c * 128 + ch * 8;
                CP16(dst, src);
            }
        }
        CP_COMMIT();
        CP_WAIT(0);
        __syncthreads();

        // A = Kt[p][d] (rows=m=p), B = Qt[q][d] (rows=n=q)
        const uint32_t uKh = sA + ((wm * 16 + off1 + j8) * KST + off2) * 2;
        const uint32_t uKl = sA + ((64 * KST + (wm * 16 + off1 + j8) * KST) + off2) * 2;
        const uint32_t uQh = sA + ((2 * 64 * KST + (wn * 32 + off2 + j8) * KST) + off1) * 2;
        const uint32_t uQl = sA + ((3 * 64 * KST + (wn * 32 + off2 + j8) * KST) + off1) * 2;

#pragma unroll
        for (int ks = 0; ks < 8; ks++) {
            uint32_t ah[4], al[4];
            LDSM4(ah, uKh + ks * 32);
            LDSM4(al, uKl + ks * 32);
#pragma unroll
            for (int qg = 0; qg < 2; qg++) {
                uint32_t bh[4], bl[4];
                uint32_t bo = (uint32_t)((qg * 16 * KST) * 2 + ks * 32);
                LDSM4(bh, uQh + bo);
                LDSM4(bl, uQl + bo);
#pragma unroll
                for (int sub = 0; sub < 2; sub++) {
                    float* cc = sacc[qg * 2 + sub];
                    MMA_BF16(cc, ah, bh[sub * 2], bh[sub * 2 + 1]);
                    MMA_BF16(cc, ah, bl[sub * 2], bl[sub * 2 + 1]);
                    MMA_BF16(cc, al, bh[sub * 2], bh[sub * 2 + 1]);
                }
            }
        }
    }

    // ---- store S with scale + mask + rel bias ----
    const float scale = 0.0625f;
#pragma unroll
    for (int na = 0; na < 4; na++) {
#pragma unroll
        for (int hf = 0; hf < 2; hf++) {
            int p = wm * 16 + (lane >> 2) + hf * 8;
            if (p < P) {
                int py = (p * 37) >> 8, px = p - py * 7;
                int fmp = fm_s[p];
#pragma unroll
                for (int e = 0; e < 2; e++) {
                    int q = wn * 32 + na * 8 + ((lane & 3) << 1) + e;
                    if (q < P) {
                        int qy = (q * 37) >> 8, qx = q - qy * 7;
                        float r = rel_s[(py - qy + 6) + 13 * (px - qx + 6)];
                        float mv = (fmp == fm_s[q]) ? 0.f : -100.f;
                        Ssm[p * SST + q] = sacc[na][hf * 2 + e] * scale + mv + r;
                    }
                }
            }
        }
    }
    __syncthreads();

    // ---- warp-parallel softmax over p (lane covers p=lane and p=lane+32) ----
#pragma unroll
    for (int cq = 0; cq < 8; cq++) {
        int q = wid * 8 + cq;
        if (q < P) {
            float v0 = Ssm[lane * SST + q];
            bool has2 = (lane + 32) < P;
            float v1 = has2 ? Ssm[(lane + 32) * SST + q] : -1e30f;
            float mx = fmaxf(v0, v1);
#pragma unroll
            for (int o = 16; o > 0; o >>= 1)
                mx = fmaxf(mx, __shfl_xor_sync(0xffffffffu, mx, o));
            float e0 = __expf(v0 - mx);
            float e1 = has2 ? __expf(v1 - mx) : 0.f;
            float s = e0 + e1;
#pragma unroll
            for (int o = 16; o > 0; o >>= 1)
                s += __shfl_xor_sync(0xffffffffu, s, o);
            float inv = 1.f / s;
            Ssm[lane * SST + q] = e0 * inv;
            if (has2) Ssm[(lane + 32) * SST + q] = e1 * inv;
        }
    }
    __syncthreads();

    // ---- load V[d][p] bf16 hi/lo via cp.async (overwrites K/Q region) ----
    __nv_bfloat16* Vh = A0;
    __nv_bfloat16* Vl = A0 + 256 * AST;
    {   // zero cols 52..63
        int r = tid;
        uint2 z2 = make_uint2(0u, 0u);
        *(uint2*)(Vh + r * AST + 52) = z2;
        *(uint2*)(Vh + r * AST + 56) = z2;
        *(uint2*)(Vh + r * AST + 60) = z2;
        *(uint2*)(Vl + r * AST + 52) = z2;
        *(uint2*)(Vl + r * AST + 56) = z2;
        *(uint2*)(Vl + r * AST + 60) = z2;
    }
    for (int i = tid; i < 6656; i += 256) {
        int arr = (i >= 3328) ? 1 : 0;
        int idx = arr ? (i - 3328) : i;
        int row = idx / 13, ch = idx - row * 13;
        uint32_t dst = (arr ? smem_u32(Vl) : smem_u32(Vh)) + row * AST * 2 + ch * 8;
        const __nv_bfloat16* src = (arr ? g_v_lo : g_v_hi) + vbase + (long)row * PNQ + ch * 4;
        CP8(dst, src);
    }
    // convert softmaxed w -> Wt[q][p] bf16 hi/lo while V loads fly
    for (int i = tid; i < 4096; i += 256) {
        int q = i >> 6, p = i & 63;
        float v = (p < P && q < P) ? Ssm[p * SST + q] : 0.f;
        __nv_bfloat16 hh = __float2bfloat16(v);
        WHI[q * WST + p] = hh;
        WLO[q * WST + p] = __float2bfloat16(v - __bfloat162float(hh));
    }
    CP_COMMIT();
    CP_WAIT(0);
    __syncthreads();

    // ---- AV: out[d][q] = sum_p V[d][p] * w[p][q] ----
    float facc[2][8][4];
#pragma unroll
    for (int a = 0; a < 2; a++)
#pragma unroll
        for (int b = 0; b < 8; b++)
#pragma unroll
            for (int k = 0; k < 4; k++) facc[a][b][k] = 0.f;

    const int d0w = wid * 32;
    const uint32_t uVh = smem_u32(Vh) + ((d0w + off1 + j8) * AST + off2) * 2;
    const uint32_t uVl = smem_u32(Vl) + ((d0w + off1 + j8) * AST + off2) * 2;
    const uint32_t uWh = smem_u32(WHI) + ((off2 + j8) * WST + off1) * 2;
    const uint32_t uWl = smem_u32(WLO) + ((off2 + j8) * WST + off1) * 2;

#pragma unroll
    for (int ks = 0; ks < 4; ks++) {
        uint32_t vh[2][4], vl[2][4];
#pragma unroll
        for (int mt = 0; mt < 2; mt++) {
            uint32_t ao = (uint32_t)((mt * 16 * AST + ks * 16) * 2);
            LDSM4(vh[mt], uVh + ao);
            LDSM4(vl[mt], uVl + ao);
        }
#pragma unroll
        for (int qg = 0; qg < 4; qg++) {
            uint32_t bh[4], bl[4];
            uint32_t bo = (uint32_t)((qg * 16 * WST + ks * 16) * 2);
            LDSM4(bh, uWh + bo);
            LDSM4(bl, uWl + bo);
#pragma unroll
            for (int mt = 0; mt < 2; mt++) {
#pragma unroll
                for (int sub = 0; sub < 2; sub++) {
                    float* cc = facc[mt][qg * 2 + sub];
                    MMA_BF16(cc, vh[mt], bh[sub * 2], bh[sub * 2 + 1]);
                    MMA_BF16(cc, vh[mt], bl[sub * 2], bl[sub * 2 + 1]);
                    MMA_BF16(cc, vl[mt], bh[sub * 2], bh[sub * 2 + 1]);
                }
            }
        }
    }
    __syncthreads();   // done reading V; region A becomes staging

    // ---- stage out[q][d] in smem ----
    float* stage = (float*)A0;
#pragma unroll
    for (int mt = 0; mt < 2; mt++) {
#pragma unroll
        for (int na = 0; na < 8; na++) {
#pragma unroll
            for (int hf = 0; hf < 2; hf++) {
                int d = d0w + mt * 16 + (lane >> 2) + hf * 8;
                int q = na * 8 + ((lane & 3) << 1);
                stage[q * OST + d] = facc[mt][na][hf * 2];
                stage[(q + 1) * OST + d] = facc[mt][na][hf * 2 + 1];
            }
        }
    }
    __syncthreads();

    // ---- coalesced bf16 hi/lo write-out ----
    const long rowbase = (long)nb * NPAD + g * 49;
    for (int q = 0; q < P; q++) {
        float v = stage[q * OST + tid];
        __nv_bfloat16 hh = __float2bfloat16(v);
        long o = (rowbase + q) * HD + h * DD + tid;
        at_hi[o] = hh;
        at_lo[o] = __float2bfloat16(v - __bfloat162float(hh));
    }
}

// ---------------- launch -----------------------------
extern "C" void kernel_launch(void* const* d_in, const int* in_sizes, int n_in,
                              void* d_out, int out_size) {
    const float* inputs = (const float*)d_in[0];
    const float* Wk = (const float*)d_in[1];
    const float* bk = (const float*)d_in[2];
    const float* Wq = (const float*)d_in[3];
    const float* bq = (const float*)d_in[4];
    const float* Wv = (const float*)d_in[5];
    const float* bv = (const float*)d_in[6];
    const float* Wo = (const float*)d_in[7];
    const float* bo = (const float*)d_in[8];
    const float* rel = (const float*)d_in[9];
    float* out = (float*)d_out;

    float *bias_c;
    __nv_bfloat16 *Wc_hi, *Wc_lo, *Wo_hi, *Wo_lo, *xt_hi, *xt_lo, *at_hi, *at_lo;
    cudaGetSymbolAddress((void**)&bias_c, g_bias_c);
    cudaGetSymbolAddress((void**)&Wc_hi, g_Wc_hi);
    cudaGetSymbolAddress((void**)&Wc_lo, g_Wc_lo);
    cudaGetSymbolAddress((void**)&Wo_hi, g_Wo_hi);
    cudaGetSymbolAddress((void**)&Wo_lo, g_Wo_lo);
    cudaGetSymbolAddress((void**)&xt_hi, g_xt_hi);
    cudaGetSymbolAddress((void**)&xt_lo, g_xt_lo);
    cudaGetSymbolAddress((void**)&at_hi, g_at_hi);
    cudaGetSymbolAddress((void**)&at_lo, g_at_lo);

    cudaFuncSetAttribute(attn_kernel, cudaFuncAttributeMaxDynamicSharedMemorySize,
                         ATTN_SMEM_BYTES);
    cudaFuncSetAttribute(gemm_kernel<128>, cudaFuncAttributeMaxDynamicSharedMemorySize,
                         GEMM_SMEM_128);
    cudaFuncSetAttribute(gemm_kernel<64>, cudaFuncAttributeMaxDynamicSharedMemorySize,
                         GEMM_SMEM_64);

    {
        long total = (long)NB * PN * DD;
        shift_conv_kernel<<<(int)((total + 255) / 256), 256>>>(inputs, xt_hi, xt_lo);
    }
    {
        long total = 6144L * 256 + 256L * 2048 + 6144;
        convert_weights<<<(int)((total + 255) / 256), 256>>>(Wk, Wq, Wv, bk, bq, bv, Wo);
    }
    // proj (BN=128, proven): emits K/Q transposed bf16 hi/lo + V bf16 hi/lo
    gemm_kernel<128><<<dim3(25, 48, 8), 256, GEMM_SMEM_128>>>(
        Wc_hi, Wc_lo, xt_hi, xt_lo, bias_c, nullptr, 256, (long)NPAD * DD, 0);
    attn_kernel<<<dim3(WIN, HEADS, NB), 256, ATTN_SMEM_BYTES>>>(rel, at_hi, at_lo);
    // outproj (BN=64): 800 blocks for better wave balance
    gemm_kernel<64><<<dim3(50, 2, 8), 256, GEMM_SMEM_64>>>(
        Wo_hi, Wo_lo, at_hi, at_lo, bo, out, 2048, (long)NPAD * HD, 1);
}

// round 17
// speedup vs baseline: 1.0362x; 1.0362x over previous
#include <cuda_runtime.h>
#include <cuda_bf16.h>
#include <cstdint>
#include <math.h>

// ---------------- problem constants ----------------
#define NB    8
#define DD    256
#define HEADS 8
#define PN    3136
#define CH    56
#define WS    7
#define P     49
#define WIN   64
#define HD    2048
#define PIX   224
#define NPAD  3200
#define PNQ   3328                    // 64 windows * 52 (aligned window stride)

#define BATCH_X   ((long)DD*PN)

// ---------------- static scratch -------------------
// K,Q in window-transposed bf16 hi/lo: [nb][s=K/Q][h][win][p(52)][d(256)]
__device__ __align__(16) __nv_bfloat16 g_kqt_hi[(long)NB * 2 * HEADS * WIN * 52 * 256];
__device__ __align__(16) __nv_bfloat16 g_kqt_lo[(long)NB * 2 * HEADS * WIN * 52 * 256];
// V in [nb][h*256+d][pnq] bf16 hi/lo
__device__ __align__(16) __nv_bfloat16 g_v_hi[(long)NB * HD * PNQ];
__device__ __align__(16) __nv_bfloat16 g_v_lo[(long)NB * HD * PNQ];
__device__ __align__(16) __nv_bfloat16 g_Wc_hi[6144 * 256];
__device__ __align__(16) __nv_bfloat16 g_Wc_lo[6144 * 256];
__device__ __align__(16) __nv_bfloat16 g_Wo_hi[256 * 2048];
__device__ __align__(16) __nv_bfloat16 g_Wo_lo[256 * 2048];
__device__ float g_bias_c[6144];
__device__ __align__(16) __nv_bfloat16 g_xt_hi[(long)NB * NPAD * DD];
__device__ __align__(16) __nv_bfloat16 g_xt_lo[(long)NB * NPAD * DD];
__device__ __align__(16) __nv_bfloat16 g_at_hi[(long)NB * NPAD * HD];
__device__ __align__(16) __nv_bfloat16 g_at_lo[(long)NB * NPAD * HD];

// ---------------- PTX helpers ----------------------
__device__ __forceinline__ uint32_t smem_u32(const void* p) {
    uint32_t a;
    asm("{ .reg .u64 t; cvta.to.shared.u64 t, %1; cvt.u32.u64 %0, t; }"
        : "=r"(a) : "l"(p));
    return a;
}

#define CP16(dst, src) \
    asm volatile("cp.async.cg.shared.global [%0], [%1], 16;" :: "r"(dst), "l"(src))
#define CP8(dst, src) \
    asm volatile("cp.async.ca.shared.global [%0], [%1], 8;" :: "r"(dst), "l"(src))
#define CP_COMMIT() asm volatile("cp.async.commit_group;" ::: "memory")
#define CP_WAIT(n)  asm volatile("cp.async.wait_group %0;" :: "n"(n) : "memory")

#define LDSM4(r, addr) \
    asm volatile("ldmatrix.sync.aligned.m8n8.x4.shared.b16 {%0,%1,%2,%3}, [%4];" \
        : "=r"((r)[0]), "=r"((r)[1]), "=r"((r)[2]), "=r"((r)[3]) : "r"(addr))

#define MMA_BF16(c, a, b0, b1) \
    asm volatile("mma.sync.aligned.m16n8k16.row.col.f32.bf16.bf16.f32 " \
        "{%0,%1,%2,%3}, {%4,%5,%6,%7}, {%8,%9}, {%0,%1,%2,%3};" \
        : "+f"((c)[0]), "+f"((c)[1]), "+f"((c)[2]), "+f"((c)[3]) \
        : "r"((a)[0]), "r"((a)[1]), "r"((a)[2]), "r"((a)[3]), "r"(b0), "r"(b1))

__device__ __forceinline__ void split_store(float x, __nv_bfloat16* hi,
                                            __nv_bfloat16* lo, long idx) {
    __nv_bfloat16 h = __float2bfloat16(x);
    hi[idx] = h;
    lo[idx] = __float2bfloat16(x - __bfloat162float(h));
}

// window-ordered column -> spatial patch index
__device__ __forceinline__ int spatial_col(int c) {
    int win = c / 49, pos = c - win * 49;
    int wy = win >> 3, wx = win & 7;
    int py = pos / 7,  px = pos - py * 7;
    return (wy * 7 + py) * CH + (wx * 7 + px);
}

// ------- fused shift + transpose + hi/lo convert -------
__global__ void shift_conv_kernel(const float* __restrict__ in,
                                  __nv_bfloat16* __restrict__ hi,
                                  __nv_bfloat16* __restrict__ lo) {
    long idx = (long)blockIdx.x * blockDim.x + threadIdx.x;
    if (idx >= (long)NB * PN * DD) return;
    int d  = (int)(idx % DD);
    int c  = (int)((idx / DD) % PN);
    int nb = (int)(idx / ((long)DD * PN));
    int win = c / 49, pos = c - win * 49;
    int wy = win >> 3, wx = win & 7;
    int py = pos / 7,  px = pos - py * 7;
    int i = wy * 7 + py, j = wx * 7 + px;
    int ch = d >> 4;
    int r = i * 4 + ((d >> 2) & 3), s = j * 4 + (d & 3);
    int rs = (r + PIX - 3) % PIX;
    int ss = (s + PIX - 3) % PIX;
    int dp = (ch << 4) + ((rs & 3) << 2) + (ss & 3);
    int pp = (rs >> 2) * CH + (ss >> 2);
    float x = in[((long)nb * DD + dp) * PN + pp];
    __nv_bfloat16 h = __float2bfloat16(x);
    long o = ((long)nb * NPAD + c) * DD + d;
    hi[o] = h;
    lo[o] = __float2bfloat16(x - __bfloat162float(h));
}

// ------------- weight conversion -------------------
__global__ void convert_weights(const float* __restrict__ Wk, const float* __restrict__ Wq,
                                const float* __restrict__ Wv, const float* __restrict__ bk,
                                const float* __restrict__ bq, const float* __restrict__ bv,
                                const float* __restrict__ Wo) {
    const long NW = 6144L * 256, NO = 256L * 2048;
    long i = (long)blockIdx.x * blockDim.x + threadIdx.x;
    if (i < NW) {
        int row = (int)(i >> 8), col = (int)(i & 255);
        const float* src = (row < 2048) ? Wk : ((row < 4096) ? Wq : Wv);
        float x = src[(long)(row & 2047) * 256 + col];
        __nv_bfloat16 h = __float2bfloat16(x);
        g_Wc_hi[i] = h;
        g_Wc_lo[i] = __float2bfloat16(x - __bfloat162float(h));
    } else if (i < NW + NO) {
        long j = i - NW;
        float x = Wo[j];
        __nv_bfloat16 h = __float2bfloat16(x);
        g_Wo_hi[j] = h;
        g_Wo_lo[j] = __float2bfloat16(x - __bfloat162float(h));
    } else if (i < NW + NO + 6144) {
        int r = (int)(i - NW - NO);
        const float* sb = (r < 2048) ? bk : ((r < 4096) ? bq : bv);
        g_bias_c[r] = sb[r & 2047];
    }
}

// ------------- HMMA bf16x3 GEMM --------------------
// 2-stage cp.async pipeline, 2 CTAs/SM. One barrier per k-tile (the trailing
// barrier is redundant: the next iteration's post-CP_WAIT barrier orders all
// compute on a stage before any cp.async overwrites it).
// mode 0: proj -> writes K/Q transposed bf16 hi/lo + V bf16 hi/lo
// mode 1: outproj -> fp32 out with spatial permutation
#define TSTRIDE 40
#define TILE_HALVES (128 * TSTRIDE)
#define STAGE_HALVES (4 * TILE_HALVES)
#define GEMM_SMEM (2 * STAGE_HALVES * 2)   // 81920 B

__global__ __launch_bounds__(256, 2) void gemm_kernel(
    const __nv_bfloat16* __restrict__ Ahi, const __nv_bfloat16* __restrict__ Alo,
    const __nv_bfloat16* __restrict__ Bhi, const __nv_bfloat16* __restrict__ Blo,
    const float* __restrict__ bias, float* __restrict__ Cbase,
    int K, long bStride, int mode)
{
    extern __shared__ __nv_bfloat16 sh[];
    const int tid = threadIdx.x;
    const int lane = tid & 31;
    const int wid = tid >> 5;
    const int wm = wid & 3;
    const int wn = wid >> 2;
    const int z  = blockIdx.z;
    const int m0g = blockIdx.y * 128;
    const int n0g = blockIdx.x * 128;
    const int T = K >> 5;

    const __nv_bfloat16* srcs[4];
    srcs[0] = Ahi + (long)m0g * K;
    srcs[1] = Alo + (long)m0g * K;
    srcs[2] = Bhi + (long)z * bStride + (long)n0g * K;
    srcs[3] = Blo + (long)z * bStride + (long)n0g * K;

    const uint32_t smu = smem_u32(sh);
    const int ldr0 = tid >> 2;
    const int ldc0 = (tid & 3) << 3;

    float acc[2][8][4];
#pragma unroll
    for (int a = 0; a < 2; a++)
#pragma unroll
        for (int b = 0; b < 8; b++)
#pragma unroll
            for (int cc = 0; cc < 4; cc++) acc[a][b][cc] = 0.f;

    const int a_r = wm * 32 + ((lane >> 3) & 1) * 8 + (lane & 7);
    const int a_c = (lane >> 4) * 8;
    const int b_r = wn * 64 + (lane >> 4) * 8 + (lane & 7);
    const int b_c = ((lane >> 3) & 1) * 8;

    // ---- preload stage 0 ----
#pragma unroll
    for (int tile = 0; tile < 4; tile++) {
#pragma unroll
        for (int j = 0; j < 2; j++) {
            int r = ldr0 + j * 64;
            uint32_t dst = smu + (tile * TILE_HALVES + r * TSTRIDE + ldc0) * 2;
            CP16(dst, srcs[tile] + (long)r * K + ldc0);
        }
    }
    CP_COMMIT();

    for (int t = 0; t < T; t++) {
        CP_WAIT(0);
        __syncthreads();   // loads visible AND prior-stage compute finished
        if (t + 1 < T) {
            const int s2 = (t + 1) & 1;
#pragma unroll
            for (int tile = 0; tile < 4; tile++) {
#pragma unroll
                for (int j = 0; j < 2; j++) {
                    int r = ldr0 + j * 64;
                    uint32_t dst = smu +
                        (s2 * STAGE_HALVES + tile * TILE_HALVES + r * TSTRIDE + ldc0) * 2;
                    CP16(dst, srcs[tile] + (long)r * K + (t + 1) * 32 + ldc0);
                }
            }
            CP_COMMIT();
        }

        const uint32_t sb = smu + ((t & 1) * STAGE_HALVES) * 2;
        const uint32_t sAh = sb;
        const uint32_t sAl = sb + TILE_HALVES * 2;
        const uint32_t sBh = sb + 2 * TILE_HALVES * 2;
        const uint32_t sBl = sb + 3 * TILE_HALVES * 2;

#pragma unroll
        for (int k16 = 0; k16 < 2; k16++) {
            uint32_t ah[2][4], al[2][4];
#pragma unroll
            for (int mt = 0; mt < 2; mt++) {
                uint32_t off = ((a_r + mt * 16) * TSTRIDE + a_c + k16 * 16) * 2;
                LDSM4(ah[mt], sAh + off);
                LDSM4(al[mt], sAl + off);
            }
#pragma unroll
            for (int nt2 = 0; nt2 < 4; nt2++) {
                uint32_t bh[4], bl[4];
                uint32_t off = ((b_r + nt2 * 16) * TSTRIDE + b_c + k16 * 16) * 2;
                LDSM4(bh, sBh + off);
                LDSM4(bl, sBl + off);
#pragma unroll
                for (int mt = 0; mt < 2; mt++) {
#pragma unroll
                    for (int sn = 0; sn < 2; sn++) {
                        float* cc = acc[mt][nt2 * 2 + sn];
                        MMA_BF16(cc, ah[mt], bh[sn * 2], bh[sn * 2 + 1]);
                        MMA_BF16(cc, ah[mt], bl[sn * 2], bl[sn * 2 + 1]);
                        MMA_BF16(cc, al[mt], bh[sn * 2], bh[sn * 2 + 1]);
                    }
                }
            }
        }
        // no trailing barrier: next iteration's barrier protects this stage
    }

    // ---- epilogue ----
#pragma unroll
    for (int mt = 0; mt < 2; mt++) {
#pragma unroll
        for (int half = 0; half < 2; half++) {
            int m = m0g + wm * 32 + mt * 16 + (lane >> 2) + half * 8;
            float bb = bias[m];
            if (mode == 0) {
                int s = m >> 11;            // 0=K 1=Q 2=V
                int hrow = m & 2047;        // h*256+d
                int d = hrow & 255;
                long kqbase = 0, vrow = 0;
                if (s < 2) kqbase = (((long)z * 2 + s) * 8 + (hrow >> 8)) * 64;
                else       vrow = ((long)z * HD + hrow) * PNQ;
#pragma unroll
                for (int nt = 0; nt < 8; nt++) {
                    int n = n0g + wn * 64 + nt * 8 + ((lane & 3) << 1);
                    if (n >= PN) continue;   // n even; n+1 < PN guaranteed
                    float v0 = acc[mt][nt][half * 2 + 0] + bb;
                    float v1 = acc[mt][nt][half * 2 + 1] + bb;
                    int w0 = n / 49, p0 = n - w0 * 49;
                    int n1 = n + 1;
                    int w1 = n1 / 49, p1 = n1 - w1 * 49;
                    if (s < 2) {
                        long i0 = ((kqbase + w0) * 52 + p0) * 256 + d;
                        long i1 = ((kqbase + w1) * 52 + p1) * 256 + d;
                        split_store(v0, g_kqt_hi, g_kqt_lo, i0);
                        split_store(v1, g_kqt_hi, g_kqt_lo, i1);
                    } else {
                        split_store(v0, g_v_hi, g_v_lo, vrow + w0 * 52 + p0);
                        split_store(v1, g_v_hi, g_v_lo, vrow + w1 * 52 + p1);
                    }
                }
            } else {
                float* C = Cbase + (long)z * BATCH_X;
                long rowoff = (long)m * PN;
#pragma unroll
                for (int nt = 0; nt < 8; nt++) {
                    int n = n0g + wn * 64 + nt * 8 + ((lane & 3) << 1);
                    if (n >= PN) continue;
                    float v0 = acc[mt][nt][half * 2 + 0] + bb;
                    float v1 = acc[mt][nt][half * 2 + 1] + bb;
                    C[rowoff + spatial_col(n)] = v0;
                    C[rowoff + spatial_col(n + 1)] = v1;
                }
            }
        }
    }
}

// ---------------- HMMA attention kernel ------------------
// Exact round-12 structure (measured 290.9us).
#define KST 136         // halves stride, Kt/Qt rows [p][d-chunk]; 272 B (16B mult)
#define AST 72          // halves stride, V rows [d][p]
#define SST 53          // floats stride for S matrix
#define WST 72          // halves stride, Wt rows ([q][p])
#define OST 260         // floats stride for output staging
#define ATTN_A_BYTES   73728
#define ATTN_S_BYTES   13568
#define ATTN_W_BYTES   9216
#define ATTN_SMEM_BYTES (ATTN_A_BYTES + ATTN_S_BYTES + 2 * ATTN_W_BYTES)

__global__ __launch_bounds__(256, 2) void attn_kernel(
    const float* __restrict__ rel_code,
    __nv_bfloat16* __restrict__ at_hi, __nv_bfloat16* __restrict__ at_lo)
{
    extern __shared__ char dyn[];
    __nv_bfloat16* A0  = (__nv_bfloat16*)dyn;
    float* Ssm  = (float*)(dyn + ATTN_A_BYTES);
    __nv_bfloat16* WHI = (__nv_bfloat16*)(dyn + ATTN_A_BYTES + ATTN_S_BYTES);
    __nv_bfloat16* WLO = WHI + 64 * WST;
    __shared__ float rel_s[169];
    __shared__ int   fm_s[49];

    const int g  = blockIdx.x;
    const int h  = blockIdx.y;
    const int nb = blockIdx.z;
    const int tid = threadIdx.x;
    const int lane = tid & 31;
    const int wid = tid >> 5;

    const long kbase = ((((long)nb * 2 + 0) * HEADS + h) * WIN + g) * 52 * 256;
    const long qbase = ((((long)nb * 2 + 1) * HEADS + h) * WIN + g) * 52 * 256;
    const long vbase = ((long)nb * HD + h * DD) * PNQ + g * 52;

    if (tid < 169) rel_s[tid] = rel_code[tid * HEADS + h];
    if (tid < P) {
        int gy = g >> 3, gx = g & 7;
        int ty = (tid * 37) >> 8, tx = tid - ty * 7;
        int rr = gy * 7 + ty, cc = gx * 7 + tx;
        int ry = (rr < 49) ? 0 : ((rr < 53) ? 1 : 2);
        int rx = (cc < 49) ? 0 : ((cc < 53) ? 1 : 2);
        fm_s[tid] = ry * 3 + rx;
    }

    const uint32_t sA = smem_u32(A0);
    const __nv_bfloat16* gsrc[4] = {
        g_kqt_hi + kbase, g_kqt_lo + kbase, g_kqt_hi + qbase, g_kqt_lo + qbase };

    const int wm = wid & 3;         // S: 4 p-warps (m-tiles of 16)
    const int wn = wid >> 2;        // S: 2 q-warps (n-tiles of 32)
    const int j8 = lane & 7;
    const int off1 = ((lane >> 3) & 1) << 3;
    const int off2 = ((lane >> 4) & 1) << 3;

    float sacc[4][4];
#pragma unroll
    for (int i = 0; i < 4; i++)
#pragma unroll
        for (int k = 0; k < 4; k++) sacc[i][k] = 0.f;

    // ---- phase 1: S = K^T Q, two d-chunks of 128 ----
    for (int c = 0; c < 2; c++) {
        __syncthreads();
        for (int i = tid; i < 4096; i += 256) {
            int arr = i >> 10, idx = i & 1023, row = idx >> 4, ch = idx & 15;
            if (row < 52) {
                uint32_t dst = sA + (arr * 64 * KST + row * KST) * 2 + ch * 16;
                const __nv_bfloat16* src = gsrc[arr] + row * 256 + c * 128 + ch * 8;
                CP16(dst, src);
            }
        }
        CP_COMMIT();
        CP_WAIT(0);
        __syncthreads();

        // A = Kt[p][d] (rows=m=p), B = Qt[q][d] (rows=n=q)
        const uint32_t uKh = sA + ((wm * 16 + off1 + j8) * KST + off2) * 2;
        const uint32_t uKl = sA + ((64 * KST + (wm * 16 + off1 + j8) * KST) + off2) * 2;
        const uint32_t uQh = sA + ((2 * 64 * KST + (wn * 32 + off2 + j8) * KST) + off1) * 2;
        const uint32_t uQl = sA + ((3 * 64 * KST + (wn * 32 + off2 + j8) * KST) + off1) * 2;

#pragma unroll
        for (int ks = 0; ks < 8; ks++) {
            uint32_t ah[4], al[4];
            LDSM4(ah, uKh + ks * 32);
            LDSM4(al, uKl + ks * 32);
#pragma unroll
            for (int qg = 0; qg < 2; qg++) {
                uint32_t bh[4], bl[4];
                uint32_t bo = (uint32_t)((qg * 16 * KST) * 2 + ks * 32);
                LDSM4(bh, uQh + bo);
                LDSM4(bl, uQl + bo);
#pragma unroll
                for (int sub = 0; sub < 2; sub++) {
                    float* cc = sacc[qg * 2 + sub];
                    MMA_BF16(cc, ah, bh[sub * 2], bh[sub * 2 + 1]);
                    MMA_BF16(cc, ah, bl[sub * 2], bl[sub * 2 + 1]);
                    MMA_BF16(cc, al, bh[sub * 2], bh[sub * 2 + 1]);
                }
            }
        }
    }

    // ---- store S with scale + mask + rel bias ----
    const float scale = 0.0625f;
#pragma unroll
    for (int na = 0; na < 4; na++) {
#pragma unroll
        for (int hf = 0; hf < 2; hf++) {
            int p = wm * 16 + (lane >> 2) + hf * 8;
            if (p < P) {
                int py = (p * 37) >> 8, px = p - py * 7;
                int fmp = fm_s[p];
#pragma unroll
                for (int e = 0; e < 2; e++) {
                    int q = wn * 32 + na * 8 + ((lane & 3) << 1) + e;
                    if (q < P) {
                        int qy = (q * 37) >> 8, qx = q - qy * 7;
                        float r = rel_s[(py - qy + 6) + 13 * (px - qx + 6)];
                        float mv = (fmp == fm_s[q]) ? 0.f : -100.f;
                        Ssm[p * SST + q] = sacc[na][hf * 2 + e] * scale + mv + r;
                    }
                }
            }
        }
    }
    __syncthreads();

    // ---- warp-parallel softmax over p (lane covers p=lane and p=lane+32) ----
#pragma unroll
    for (int cq = 0; cq < 8; cq++) {
        int q = wid * 8 + cq;
        if (q < P) {
            float v0 = Ssm[lane * SST + q];
            bool has2 = (lane + 32) < P;
            float v1 = has2 ? Ssm[(lane + 32) * SST + q] : -1e30f;
            float mx = fmaxf(v0, v1);
#pragma unroll
            for (int o = 16; o > 0; o >>= 1)
                mx = fmaxf(mx, __shfl_xor_sync(0xffffffffu, mx, o));
            float e0 = __expf(v0 - mx);
            float e1 = has2 ? __expf(v1 - mx) : 0.f;
            float s = e0 + e1;
#pragma unroll
            for (int o = 16; o > 0; o >>= 1)
                s += __shfl_xor_sync(0xffffffffu, s, o);
            float inv = 1.f / s;
            Ssm[lane * SST + q] = e0 * inv;
            if (has2) Ssm[(lane + 32) * SST + q] = e1 * inv;
        }
    }
    __syncthreads();

    // ---- load V[d][p] bf16 hi/lo via cp.async (overwrites K/Q region) ----
    __nv_bfloat16* Vh = A0;
    __nv_bfloat16* Vl = A0 + 256 * AST;
    {   // zero cols 52..63
        int r = tid;
        uint2 z2 = make_uint2(0u, 0u);
        *(uint2*)(Vh + r * AST + 52) = z2;
        *(uint2*)(Vh + r * AST + 56) = z2;
        *(uint2*)(Vh + r * AST + 60) = z2;
        *(uint2*)(Vl + r * AST + 52) = z2;
        *(uint2*)(Vl + r * AST + 56) = z2;
        *(uint2*)(Vl + r * AST + 60) = z2;
    }
    for (int i = tid; i < 6656; i += 256) {
        int arr = (i >= 3328) ? 1 : 0;
        int idx = arr ? (i - 3328) : i;
        int row = idx / 13, ch = idx - row * 13;
        uint32_t dst = (arr ? smem_u32(Vl) : smem_u32(Vh)) + row * AST * 2 + ch * 8;
        const __nv_bfloat16* src = (arr ? g_v_lo : g_v_hi) + vbase + (long)row * PNQ + ch * 4;
        CP8(dst, src);
    }
    // convert softmaxed w -> Wt[q][p] bf16 hi/lo while V loads fly
    for (int i = tid; i < 4096; i += 256) {
        int q = i >> 6, p = i & 63;
        float v = (p < P && q < P) ? Ssm[p * SST + q] : 0.f;
        __nv_bfloat16 hh = __float2bfloat16(v);
        WHI[q * WST + p] = hh;
        WLO[q * WST + p] = __float2bfloat16(v - __bfloat162float(hh));
    }
    CP_COMMIT();
    CP_WAIT(0);
    __syncthreads();

    // ---- AV: out[d][q] = sum_p V[d][p] * w[p][q] ----
    float facc[2][8][4];
#pragma unroll
    for (int a = 0; a < 2; a++)
#pragma unroll
        for (int b = 0; b < 8; b++)
#pragma unroll
            for (int k = 0; k < 4; k++) facc[a][b][k] = 0.f;

    const int d0w = wid * 32;
    const uint32_t uVh = smem_u32(Vh) + ((d0w + off1 + j8) * AST + off2) * 2;
    const uint32_t uVl = smem_u32(Vl) + ((d0w + off1 + j8) * AST + off2) * 2;
    const uint32_t uWh = smem_u32(WHI) + ((off2 + j8) * WST + off1) * 2;
    const uint32_t uWl = smem_u32(WLO) + ((off2 + j8) * WST + off1) * 2;

#pragma unroll
    for (int ks = 0; ks < 4; ks++) {
        uint32_t vh[2][4], vl[2][4];
#pragma unroll
        for (int mt = 0; mt < 2; mt++) {
            uint32_t ao = (uint32_t)((mt * 16 * AST + ks * 16) * 2);
            LDSM4(vh[mt], uVh + ao);
            LDSM4(vl[mt], uVl + ao);
        }
#pragma unroll
        for (int qg = 0; qg < 4; qg++) {
            uint32_t bh[4], bl[4];
            uint32_t bo = (uint32_t)((qg * 16 * WST + ks * 16) * 2);
            LDSM4(bh, uWh + bo);
            LDSM4(bl, uWl + bo);
#pragma unroll
            for (int mt = 0; mt < 2; mt++) {
#pragma unroll
                for (int sub = 0; sub < 2; sub++) {
                    float* cc = facc[mt][qg * 2 + sub];
                    MMA_BF16(cc, vh[mt], bh[sub * 2], bh[sub * 2 + 1]);
                    MMA_BF16(cc, vh[mt], bl[sub * 2], bl[sub * 2 + 1]);
                    MMA_BF16(cc, vl[mt], bh[sub * 2], bh[sub * 2 + 1]);
                }
            }
        }
    }
    __syncthreads();   // done reading V; region A becomes staging

    // ---- stage out[q][d] in smem ----
    float* stage = (float*)A0;
#pragma unroll
    for (int mt = 0; mt < 2; mt++) {
#pragma unroll
        for (int na = 0; na < 8; na++) {
#pragma unroll
            for (int hf = 0; hf < 2; hf++) {
                int d = d0w + mt * 16 + (lane >> 2) + hf * 8;
                int q = na * 8 + ((lane & 3) << 1);
                stage[q * OST + d] = facc[mt][na][hf * 2];
                stage[(q + 1) * OST + d] = facc[mt][na][hf * 2 + 1];
            }
        }
    }
    __syncthreads();

    // ---- coalesced bf16 hi/lo write-out ----
    const long rowbase = (long)nb * NPAD + g * 49;
    for (int q = 0; q < P; q++) {
        float v = stage[q * OST + tid];
        __nv_bfloat16 hh = __float2bfloat16(v);
        long o = (rowbase + q) * HD + h * DD + tid;
        at_hi[o] = hh;
        at_lo[o] = __float2bfloat16(v - __bfloat162float(hh));
    }
}

// ---------------- launch -----------------------------
extern "C" void kernel_launch(void* const* d_in, const int* in_sizes, int n_in,
                              void* d_out, int out_size) {
    const float* inputs = (const float*)d_in[0];
    const float* Wk = (const float*)d_in[1];
    const float* bk = (const float*)d_in[2];
    const float* Wq = (const float*)d_in[3];
    const float* bq = (const float*)d_in[4];
    const float* Wv = (const float*)d_in[5];
    const float* bv = (const float*)d_in[6];
    const float* Wo = (const float*)d_in[7];
    const float* bo = (const float*)d_in[8];
    const float* rel = (const float*)d_in[9];
    float* out = (float*)d_out;

    float *bias_c;
    __nv_bfloat16 *Wc_hi, *Wc_lo, *Wo_hi, *Wo_lo, *xt_hi, *xt_lo, *at_hi, *at_lo;
    cudaGetSymbolAddress((void**)&bias_c, g_bias_c);
    cudaGetSymbolAddress((void**)&Wc_hi, g_Wc_hi);
    cudaGetSymbolAddress((void**)&Wc_lo, g_Wc_lo);
    cudaGetSymbolAddress((void**)&Wo_hi, g_Wo_hi);
    cudaGetSymbolAddress((void**)&Wo_lo, g_Wo_lo);
    cudaGetSymbolAddress((void**)&xt_hi, g_xt_hi);
    cudaGetSymbolAddress((void**)&xt_lo, g_xt_lo);
    cudaGetSymbolAddress((void**)&at_hi, g_at_hi);
    cudaGetSymbolAddress((void**)&at_lo, g_at_lo);

    cudaFuncSetAttribute(attn_kernel, cudaFuncAttributeMaxDynamicSharedMemorySize,
                         ATTN_SMEM_BYTES);
    cudaFuncSetAttribute(gemm_kernel, cudaFuncAttributeMaxDynamicSharedMemorySize,
                         GEMM_SMEM);

    {
        long total = (long)NB * PN * DD;
        shift_conv_kernel<<<(int)((total + 255) / 256), 256>>>(inputs, xt_hi, xt_lo);
    }
    {
        long total = 6144L * 256 + 256L * 2048 + 6144;
        convert_weights<<<(int)((total + 255) / 256), 256>>>(Wk, Wq, Wv, bk, bq, bv, Wo);
    }
    // proj: emits K/Q transposed bf16 hi/lo + V bf16 hi/lo (Cbase unused)
    gemm_kernel<<<dim3(25, 48, 8), 256, GEMM_SMEM>>>(Wc_hi, Wc_lo, xt_hi, xt_lo,
                                                     bias_c, nullptr, 256,
                                                     (long)NPAD * DD, 0);
    attn_kernel<<<dim3(WIN, HEADS, NB), 256, ATTN_SMEM_BYTES>>>(rel, at_hi, at_lo);
    gemm_kernel<<<dim3(25, 2, 8), 256, GEMM_SMEM>>>(Wo_hi, Wo_lo, at_hi, at_lo,
                                                    bo, out, 2048, (long)NPAD * HD, 1);
}